// round 6
// baseline (speedup 1.0000x reference)
#include <cuda_runtime.h>
#include <float.h>

#define TT   3
#define HH   192
#define WW   192
#define CC   64
#define HWSZ (HH*WW)
#define NHC  24
#define NWC  24
#define Q1   (TT*NHC*NWC)   // 1728
#define NHF  48
#define NWF  48
#define QF   (TT*NHF*NWF)   // 6912
#define KK   7
#define SS   192            // candidates per query

// scratch (static __device__ arrays — allowed; no runtime allocation)
__device__ float g_v0t[TT*HWSZ*CC];
__device__ float g_v1t[TT*HWSZ*CC];
__device__ float g_sd[Q1*SS];
__device__ int   g_inds[Q1*KK*3];

__device__ __forceinline__ int refl(int i, int L) {
    i = i < 0 ? -i : i;
    return (i >= L) ? (2*(L-1) - i) : i;
}

// ---------------------------------------------------------------------------
// Transpose (T,C,H,W) -> (T,H,W,C), channels-last, for both videos.
// ---------------------------------------------------------------------------
__global__ void __launch_bounds__(256) transpose_kernel(const float* __restrict__ v0,
                                                        const float* __restrict__ v1) {
    const float* src = (blockIdx.z == 0) ? v0 : v1;
    float* dst       = (blockIdx.z == 0) ? g_v0t : g_v1t;
    const int t    = blockIdx.y;
    const int pix0 = blockIdx.x * 32;

    __shared__ float tile[CC][33];
    const int tx  = threadIdx.x & 31;
    const int grp = threadIdx.x >> 5;   // 0..7

    #pragma unroll
    for (int cc = 0; cc < CC; cc += 8) {
        int c = cc + grp;
        tile[c][tx] = src[((size_t)(t*CC + c))*HWSZ + pix0 + tx];
    }
    __syncthreads();
    #pragma unroll
    for (int i = 0; i < 8; ++i) {
        int idx = i*256 + threadIdx.x;        // 0..2047
        int pix = idx >> 6;                   // 0..31
        int ch  = idx & 63;
        dst[((size_t)t*HWSZ + pix0 + pix)*CC + ch] = tile[ch][pix];
    }
}

// ---------------------------------------------------------------------------
// Stage 1a v3: candidate distances with XLA-replicating fp32 arithmetic.
// grid (6, 24, 9): block = (4 adjacent queries qj0..qj0+3, row qi, z = qt*3+t).
// 128 threads = 4 warps; warp u handles query qj0+u. Lane = dyi*4 + pair;
// each thread owns 2 candidates (dxi = 2*pair, 2*pair+1).
// Shared candidate window loaded ONCE: 14 row-slots x 38 col-slots x 64ch
// (slot r <-> refl(qh-7+r), slot s <-> refl(qw0-7+s); compute-side slots are
// simply (dyi+dri) and (8u + dxi + ox)).
// Per candidate, per offset (dri,ox): p = sequential fma chain over c=0..63,
// then acc += p in (dri major, ox ascending) order. DO NOT REORDER — this
// reproduces the reference's fp tie resolution bit-for-bit.
// ---------------------------------------------------------------------------
#define CSTR2   68                    // col-slot stride (floats)
#define ROWSTR2 (38*CSTR2 + 12)       // 2596 floats; bank-conflict-free reads
#define SV_BYTES (14*ROWSTR2*4)       // 145376 bytes dynamic smem

__global__ void __launch_bounds__(128) stage1a_kernel() {
    extern __shared__ float sv[];
    const int qj0 = blockIdx.x * 4;
    const int qi  = blockIdx.y;
    const int zz  = blockIdx.z;       // qt*3 + t
    const int qt  = zz / 3;
    const int t   = zz % 3;
    const int qh  = qi * 8;
    const int qw0 = qj0 * 8;

    const int tid  = threadIdx.x;
    const int u    = tid >> 5;        // query within block (warp id)
    const int lane = tid & 31;
    const int dyi  = lane >> 2;       // 0..7
    const int pair = lane & 3;        // 0..3 -> dxi {2p, 2p+1}

    // cooperative load of the shared candidate window (once)
    const float* v1base = g_v1t + (size_t)t*HWSZ*CC;
    for (int i = tid; i < 14*38*16; i += 128) {
        int r   = i / (38*16);
        int rem = i % (38*16);
        int s   = rem >> 4;
        int c4  = rem & 15;
        int y = refl(qh - 7 + r, HH);
        int x = refl(qw0 - 7 + s, WW);
        float4 v = reinterpret_cast<const float4*>(v1base + ((size_t)y*WW + x)*CC)[c4];
        *reinterpret_cast<float4*>(sv + r*ROWSTR2 + s*CSTR2 + c4*4) = v;
    }
    __syncthreads();

    const int q  = qt*(NHC*NWC) + qi*NWC + (qj0 + u);
    const int qw = qw0 + u*8;

    // query patch col coords (uniform within warp)
    int xq[7];
    #pragma unroll
    for (int ox = 0; ox < 7; ++ox) xq[ox] = refl(qw + ox - 3, WW);
    const float* v0base = g_v0t + (size_t)qt*HWSZ*CC;

    float acc0 = 0.f, acc1 = 0.f;
    const float* svw = sv + (8*u + 2*pair)*CSTR2;

    for (int dri = 0; dri < 7; ++dri) {
        const int yq = refl(qh + dri - 3, HH);
        const float* qrow = v0base + (size_t)yq*WW*CC;
        const float* vrow = svw + (dyi + dri)*ROWSTR2;

        float p0[7], p1[7];
        #pragma unroll
        for (int ox = 0; ox < 7; ++ox) { p0[ox] = 0.f; p1[ox] = 0.f; }

        #pragma unroll 2
        for (int c4 = 0; c4 < 16; ++c4) {
            float4 w[8];
            #pragma unroll
            for (int j = 0; j < 8; ++j)
                w[j] = *reinterpret_cast<const float4*>(vrow + j*CSTR2 + c4*4);
            #pragma unroll
            for (int ox = 0; ox < 7; ++ox) {
                float4 a  = reinterpret_cast<const float4*>(qrow + (size_t)xq[ox]*CC)[c4];
                float4 b0 = w[ox];      // candidate dxi = 2*pair
                float4 b1 = w[ox + 1];  // candidate dxi = 2*pair + 1
                p0[ox] = fmaf(a.x, b0.x, p0[ox]);
                p0[ox] = fmaf(a.y, b0.y, p0[ox]);
                p0[ox] = fmaf(a.z, b0.z, p0[ox]);
                p0[ox] = fmaf(a.w, b0.w, p0[ox]);
                p1[ox] = fmaf(a.x, b1.x, p1[ox]);
                p1[ox] = fmaf(a.y, b1.y, p1[ox]);
                p1[ox] = fmaf(a.z, b1.z, p1[ox]);
                p1[ox] = fmaf(a.w, b1.w, p1[ox]);
            }
        }
        #pragma unroll
        for (int ox = 0; ox < 7; ++ox) { acc0 += p0[ox]; acc1 += p1[ox]; }
    }

    float2 res = make_float2(acc0, acc1);
    *reinterpret_cast<float2*>(&g_sd[q*SS + t*64 + dyi*8 + 2*pair]) = res;
}

// ---------------------------------------------------------------------------
// Stage 1b: stable top-7 per query (argmax with lowest-index tie break,
// exactly lax.top_k semantics). 192 threads per query.
// ---------------------------------------------------------------------------
__global__ void __launch_bounds__(192) stage1b_kernel() {
    const int q  = blockIdx.x;
    const int rr = q % (NHC*NWC);
    const int qh = (rr / NWC) * 8;
    const int qw = (rr % NWC) * 8;

    __shared__ float sd[SS];
    __shared__ float rv[256];
    __shared__ int   ri[256];

    const int tid = threadIdx.x;
    sd[tid] = g_sd[q*SS + tid];
    __syncthreads();

    for (int k = 0; k < KK; ++k) {
        rv[tid] = sd[tid]; ri[tid] = tid;
        if (tid < 64) { rv[192 + tid] = -FLT_MAX; ri[192 + tid] = 255; }
        __syncthreads();
        #pragma unroll
        for (int s = 128; s >= 1; s >>= 1) {
            if (tid < s) {
                float v2 = rv[tid + s]; int i2 = ri[tid + s];
                if (v2 > rv[tid] || (v2 == rv[tid] && i2 < ri[tid])) {
                    rv[tid] = v2; ri[tid] = i2;
                }
            }
            __syncthreads();
        }
        if (tid == 0) {
            int sel = ri[0];
            sd[sel] = -FLT_MAX;
            int base = (q*KK + k)*3;
            g_inds[base + 0] = sel >> 6;                   // ct
            g_inds[base + 1] = qh + ((sel >> 3) & 7) - 4;  // ch (raw)
            g_inds[base + 2] = qw + (sel & 7) - 4;         // cw (raw)
        }
        __syncthreads();
    }
}

// ---------------------------------------------------------------------------
// Stage 2+3 fused v3: upsample indices + refine dists, with a cooperative
// per-block offset table (kills the per-lane redundant refl/address ALU).
// block = 224 threads (7 warps) per fine query; warp k handles candidate k.
// ---------------------------------------------------------------------------
__global__ void __launch_bounds__(224) stage3_kernel(float* __restrict__ out) {
    const int q  = blockIdx.x;
    const int ft = q / (NHF*NWF);
    const int rr = q % (NHF*NWF);
    const int fi = rr / NWF, fj = rr % NWF;
    const int fh = fi*4, fw = fj*4;

    __shared__ float sp[49*CC];
    __shared__ int   scand[KK*3];
    __shared__ int   soff[KK*49];

    const int tid = threadIdx.x;
    for (int i = tid; i < 49*CC; i += 224) {
        int o = i >> 6, c = i & 63;
        int y = refl(fh + (o/7) - 3, HH);
        int x = refl(fw + (o%7) - 3, WW);
        sp[i] = g_v0t[((size_t)ft*HWSZ + (size_t)y*WW + x)*CC + c];
    }
    if (tid < KK) {
        int it, ih, iw;
        if (tid == 0) { it = ft; ih = fh; iw = fw; }
        else {
            int ci = min(fi >> 1, NHC - 1);
            int cj = min(fj >> 1, NWC - 1);
            int qlin = ft*NHC*NWC + ci*NWC + cj;
            int b = (qlin*KK + tid)*3;
            it = g_inds[b + 0];
            ih = refl(g_inds[b + 1] + (fh - ci*8), HH);
            iw = refl(g_inds[b + 2] + (fw - cj*8), WW);
        }
        scand[tid*3 + 0] = it;
        scand[tid*3 + 1] = ih;
        scand[tid*3 + 2] = iw;
        // inds_f (as float), laid out after dists_f
        size_t ob = (size_t)QF*KK + ((size_t)q*KK + tid)*3;
        out[ob + 0] = (float)it;
        out[ob + 1] = (float)ih;
        out[ob + 2] = (float)iw;
    }
    __syncthreads();

    // cooperative offset table: soff[k][o] = y1*W + x1
    for (int i = tid; i < KK*49; i += 224) {
        int k = i / 49, o = i % 49;
        int y1 = refl(scand[k*3 + 1] + o/7 - 3, HH);
        int x1 = refl(scand[k*3 + 2] + o%7 - 3, WW);
        soff[i] = y1*WW + x1;
    }
    __syncthreads();

    const int warp = tid >> 5;
    const int lane = tid & 31;
    const int it = scand[warp*3 + 0];
    const float* v1b = g_v1t + (size_t)it*HWSZ*CC + 2*lane;
    const int* mysoff = soff + warp*49;
    const float* spl = sp + 2*lane;

    float2 acc = make_float2(0.f, 0.f);
    #pragma unroll 7
    for (int o = 0; o < 49; ++o) {
        float2 wv = *reinterpret_cast<const float2*>(v1b + (size_t)mysoff[o]*CC);
        float2 pv = *reinterpret_cast<const float2*>(spl + o*CC);
        acc.x = fmaf(pv.x, wv.x, acc.x);
        acc.y = fmaf(pv.y, wv.y, acc.y);
    }
    float v = acc.x + acc.y;
    #pragma unroll
    for (int s = 16; s > 0; s >>= 1)
        v += __shfl_down_sync(0xffffffffu, v, s);
    if (lane == 0)
        out[(size_t)q*KK + warp] = v;
}

// ---------------------------------------------------------------------------
extern "C" void kernel_launch(void* const* d_in, const int* in_sizes, int n_in,
                              void* d_out, int out_size) {
    const float* vid0 = (const float*)d_in[0];
    const float* vid1 = (const float*)d_in[1];
    // d_in[2] = flows, unused by the reference

    // allow >48KB dynamic smem for stage1a (attribute set; not a stream op,
    // capture-safe and idempotent)
    cudaFuncSetAttribute(stage1a_kernel,
                         cudaFuncAttributeMaxDynamicSharedMemorySize, SV_BYTES);

    dim3 tgrid(HWSZ/32, TT, 2);
    transpose_kernel<<<tgrid, 256>>>(vid0, vid1);
    stage1a_kernel<<<dim3(NWC/4, NHC, TT*TT), 128, SV_BYTES>>>();
    stage1b_kernel<<<Q1, 192>>>();
    stage3_kernel<<<QF, 224>>>((float*)d_out);
}

// round 7
// speedup vs baseline: 1.4168x; 1.4168x over previous
#include <cuda_runtime.h>
#include <float.h>

#define TT   3
#define HH   192
#define WW   192
#define CC   64
#define HWSZ (HH*WW)
#define NHC  24
#define NWC  24
#define Q1   (TT*NHC*NWC)   // 1728
#define NHF  48
#define NWF  48
#define QF   (TT*NHF*NWF)   // 6912
#define KK   7
#define SS   192            // candidates per query

// scratch (static __device__ arrays — allowed; no runtime allocation)
__device__ float g_v0t[TT*HWSZ*CC];
__device__ float g_v1t[TT*HWSZ*CC];
__device__ float g_sd[Q1*SS];
__device__ int   g_inds[Q1*KK*3];

__device__ __forceinline__ int refl(int i, int L) {
    i = i < 0 ? -i : i;
    return (i >= L) ? (2*(L-1) - i) : i;
}

// ---------------------------------------------------------------------------
// Transpose (T,C,H,W) -> (T,H,W,C), channels-last, for both videos.
// ---------------------------------------------------------------------------
__global__ void __launch_bounds__(256) transpose_kernel(const float* __restrict__ v0,
                                                        const float* __restrict__ v1) {
    const float* src = (blockIdx.z == 0) ? v0 : v1;
    float* dst       = (blockIdx.z == 0) ? g_v0t : g_v1t;
    const int t    = blockIdx.y;
    const int pix0 = blockIdx.x * 32;

    __shared__ float tile[CC][33];
    const int tx  = threadIdx.x & 31;
    const int grp = threadIdx.x >> 5;   // 0..7

    #pragma unroll
    for (int cc = 0; cc < CC; cc += 8) {
        int c = cc + grp;
        tile[c][tx] = src[((size_t)(t*CC + c))*HWSZ + pix0 + tx];
    }
    __syncthreads();
    #pragma unroll
    for (int i = 0; i < 8; ++i) {
        int idx = i*256 + threadIdx.x;        // 0..2047
        int pix = idx >> 6;                   // 0..31
        int ch  = idx & 63;
        dst[((size_t)t*HWSZ + pix0 + pix)*CC + ch] = tile[ch][pix];
    }
}

// ---------------------------------------------------------------------------
// Stage 1a v4: shared candidate window + SMEM query patches.
// grid (6, 24, 9): block = (4 adjacent queries, row qi, z = qt*3+t).
// 128 threads = 4 warps; warp u handles query qj0+u. lane = dyi*4 + pair;
// each thread owns 2 candidates (dxi = 2*pair, 2*pair+1).
// Dynamic smem: sv = 14 row-slots x 38 col-slots x 64ch window (142 KB),
// then sq = 4 query patches (49x64 each, 49 KB). Inner loop is pure LDS+FMA.
// Per candidate, per offset (dri,ox): p = sequential fma chain over c=0..63,
// then acc += p in (dri major, ox ascending) order. DO NOT REORDER — this
// reproduces the reference's fp tie resolution bit-for-bit.
// ---------------------------------------------------------------------------
#define CSTR2   68                    // col-slot stride (floats)
#define ROWSTR2 (38*CSTR2 + 12)       // 2596 floats; conflict-free reads
#define SV_FLOATS (14*ROWSTR2)        // 36344
#define SQ_FLOATS (4*49*CC)           // 12544
#define SMEM1A_BYTES ((SV_FLOATS + SQ_FLOATS)*4)   // 195552 bytes

__global__ void __launch_bounds__(128) stage1a_kernel() {
    extern __shared__ float sv[];
    float* sq = sv + SV_FLOATS;

    const int qj0 = blockIdx.x * 4;
    const int qi  = blockIdx.y;
    const int zz  = blockIdx.z;       // qt*3 + t
    const int qt  = zz / 3;
    const int t   = zz % 3;
    const int qh  = qi * 8;
    const int qw0 = qj0 * 8;

    const int tid  = threadIdx.x;
    const int u    = tid >> 5;        // query within block (warp id)
    const int lane = tid & 31;
    const int dyi  = lane >> 2;       // 0..7
    const int pair = lane & 3;        // 0..3 -> dxi {2p, 2p+1}

    // cooperative load: candidate window (once)
    const float* v1base = g_v1t + (size_t)t*HWSZ*CC;
    for (int i = tid; i < 14*38*16; i += 128) {
        int r   = i / (38*16);
        int rem = i % (38*16);
        int s   = rem >> 4;
        int c4  = rem & 15;
        int y = refl(qh - 7 + r, HH);
        int x = refl(qw0 - 7 + s, WW);
        float4 v = reinterpret_cast<const float4*>(v1base + ((size_t)y*WW + x)*CC)[c4];
        *reinterpret_cast<float4*>(sv + r*ROWSTR2 + s*CSTR2 + c4*4) = v;
    }
    // cooperative load: 4 query patches
    const float* v0base = g_v0t + (size_t)qt*HWSZ*CC;
    for (int i = tid; i < 4*49*16; i += 128) {
        int u2  = i / (49*16);
        int rem = i % (49*16);
        int o   = rem >> 4;
        int c4  = rem & 15;
        int y = refl(qh + (o/7) - 3, HH);
        int x = refl(qw0 + 8*u2 + (o%7) - 3, WW);
        float4 v = reinterpret_cast<const float4*>(v0base + ((size_t)y*WW + x)*CC)[c4];
        *reinterpret_cast<float4*>(sq + u2*(49*CC) + o*CC + c4*4) = v;
    }
    __syncthreads();

    const int q = qt*(NHC*NWC) + qi*NWC + (qj0 + u);

    float acc0 = 0.f, acc1 = 0.f;
    const float* svw   = sv + (8*u + 2*pair)*CSTR2;
    const float* qbase = sq + u*(49*CC);

    for (int dri = 0; dri < 7; ++dri) {
        const float* qrow = qbase + dri*7*CC;
        const float* vrow = svw + (dyi + dri)*ROWSTR2;

        float p0[7], p1[7];
        #pragma unroll
        for (int ox = 0; ox < 7; ++ox) { p0[ox] = 0.f; p1[ox] = 0.f; }

        #pragma unroll 2
        for (int c4 = 0; c4 < 16; ++c4) {
            float4 w[8];
            #pragma unroll
            for (int j = 0; j < 8; ++j)
                w[j] = *reinterpret_cast<const float4*>(vrow + j*CSTR2 + c4*4);
            #pragma unroll
            for (int ox = 0; ox < 7; ++ox) {
                float4 a  = *reinterpret_cast<const float4*>(qrow + ox*CC + c4*4);
                float4 b0 = w[ox];      // candidate dxi = 2*pair
                float4 b1 = w[ox + 1];  // candidate dxi = 2*pair + 1
                p0[ox] = fmaf(a.x, b0.x, p0[ox]);
                p0[ox] = fmaf(a.y, b0.y, p0[ox]);
                p0[ox] = fmaf(a.z, b0.z, p0[ox]);
                p0[ox] = fmaf(a.w, b0.w, p0[ox]);
                p1[ox] = fmaf(a.x, b1.x, p1[ox]);
                p1[ox] = fmaf(a.y, b1.y, p1[ox]);
                p1[ox] = fmaf(a.z, b1.z, p1[ox]);
                p1[ox] = fmaf(a.w, b1.w, p1[ox]);
            }
        }
        #pragma unroll
        for (int ox = 0; ox < 7; ++ox) { acc0 += p0[ox]; acc1 += p1[ox]; }
    }

    float2 res = make_float2(acc0, acc1);
    *reinterpret_cast<float2*>(&g_sd[q*SS + t*64 + dyi*8 + 2*pair]) = res;
}

// ---------------------------------------------------------------------------
// Stage 1b v2: warp-per-query top-7 via shuffles (no block syncs).
// grid 216 x 256 threads; warp w handles query blockIdx.x*8 + w.
// Stable: ties -> lowest candidate index (lax.top_k semantics).
// ---------------------------------------------------------------------------
__global__ void __launch_bounds__(256) stage1b_kernel() {
    const int lane = threadIdx.x & 31;
    const int q = blockIdx.x*8 + (threadIdx.x >> 5);
    const int rr = q % (NHC*NWC);
    const int qh = (rr / NWC) * 8;
    const int qw = (rr % NWC) * 8;

    float v[6];
    #pragma unroll
    for (int j = 0; j < 6; ++j) v[j] = g_sd[q*SS + j*32 + lane];

    #pragma unroll 1
    for (int k = 0; k < KK; ++k) {
        // lane-local argmax (strict > keeps lowest index since idx grows with j)
        float bv = v[0]; int bi = lane;
        #pragma unroll
        for (int j = 1; j < 6; ++j) {
            if (v[j] > bv) { bv = v[j]; bi = j*32 + lane; }
        }
        // warp argmax with lowest-index tie break
        #pragma unroll
        for (int s = 16; s > 0; s >>= 1) {
            float ov = __shfl_xor_sync(0xffffffffu, bv, s);
            int   oi = __shfl_xor_sync(0xffffffffu, bi, s);
            if (ov > bv || (ov == bv && oi < bi)) { bv = ov; bi = oi; }
        }
        if (lane == 0) {
            int base = (q*KK + k)*3;
            g_inds[base + 0] = bi >> 6;                   // ct
            g_inds[base + 1] = qh + ((bi >> 3) & 7) - 4;  // ch (raw)
            g_inds[base + 2] = qw + (bi & 7) - 4;         // cw (raw)
        }
        // knock out the winner
        if ((bi & 31) == lane) {
            int jj = bi >> 5;
            #pragma unroll
            for (int j = 0; j < 6; ++j) if (j == jj) v[j] = -FLT_MAX;
        }
    }
}

// ---------------------------------------------------------------------------
// Stage 2+3 fused: upsample indices + refine dists, cooperative offset table.
// block = 224 threads (7 warps) per fine query; warp k handles candidate k.
// ---------------------------------------------------------------------------
__global__ void __launch_bounds__(224) stage3_kernel(float* __restrict__ out) {
    const int q  = blockIdx.x;
    const int ft = q / (NHF*NWF);
    const int rr = q % (NHF*NWF);
    const int fi = rr / NWF, fj = rr % NWF;
    const int fh = fi*4, fw = fj*4;

    __shared__ float sp[49*CC];
    __shared__ int   scand[KK*3];
    __shared__ int   soff[KK*49];

    const int tid = threadIdx.x;
    for (int i = tid; i < 49*CC; i += 224) {
        int o = i >> 6, c = i & 63;
        int y = refl(fh + (o/7) - 3, HH);
        int x = refl(fw + (o%7) - 3, WW);
        sp[i] = g_v0t[((size_t)ft*HWSZ + (size_t)y*WW + x)*CC + c];
    }
    if (tid < KK) {
        int it, ih, iw;
        if (tid == 0) { it = ft; ih = fh; iw = fw; }
        else {
            int ci = min(fi >> 1, NHC - 1);
            int cj = min(fj >> 1, NWC - 1);
            int qlin = ft*NHC*NWC + ci*NWC + cj;
            int b = (qlin*KK + tid)*3;
            it = g_inds[b + 0];
            ih = refl(g_inds[b + 1] + (fh - ci*8), HH);
            iw = refl(g_inds[b + 2] + (fw - cj*8), WW);
        }
        scand[tid*3 + 0] = it;
        scand[tid*3 + 1] = ih;
        scand[tid*3 + 2] = iw;
        // inds_f (as float), laid out after dists_f
        size_t ob = (size_t)QF*KK + ((size_t)q*KK + tid)*3;
        out[ob + 0] = (float)it;
        out[ob + 1] = (float)ih;
        out[ob + 2] = (float)iw;
    }
    __syncthreads();

    // cooperative offset table: soff[k][o] = y1*W + x1
    for (int i = tid; i < KK*49; i += 224) {
        int k = i / 49, o = i % 49;
        int y1 = refl(scand[k*3 + 1] + o/7 - 3, HH);
        int x1 = refl(scand[k*3 + 2] + o%7 - 3, WW);
        soff[i] = y1*WW + x1;
    }
    __syncthreads();

    const int warp = tid >> 5;
    const int lane = tid & 31;
    const int it = scand[warp*3 + 0];
    const float* v1b = g_v1t + (size_t)it*HWSZ*CC + 2*lane;
    const int* mysoff = soff + warp*49;
    const float* spl = sp + 2*lane;

    float2 acc = make_float2(0.f, 0.f);
    #pragma unroll 7
    for (int o = 0; o < 49; ++o) {
        float2 wv = *reinterpret_cast<const float2*>(v1b + (size_t)mysoff[o]*CC);
        float2 pv = *reinterpret_cast<const float2*>(spl + o*CC);
        acc.x = fmaf(pv.x, wv.x, acc.x);
        acc.y = fmaf(pv.y, wv.y, acc.y);
    }
    float v = acc.x + acc.y;
    #pragma unroll
    for (int s = 16; s > 0; s >>= 1)
        v += __shfl_down_sync(0xffffffffu, v, s);
    if (lane == 0)
        out[(size_t)q*KK + warp] = v;
}

// ---------------------------------------------------------------------------
extern "C" void kernel_launch(void* const* d_in, const int* in_sizes, int n_in,
                              void* d_out, int out_size) {
    const float* vid0 = (const float*)d_in[0];
    const float* vid1 = (const float*)d_in[1];
    // d_in[2] = flows, unused by the reference

    cudaFuncSetAttribute(stage1a_kernel,
                         cudaFuncAttributeMaxDynamicSharedMemorySize, SMEM1A_BYTES);

    dim3 tgrid(HWSZ/32, TT, 2);
    transpose_kernel<<<tgrid, 256>>>(vid0, vid1);
    stage1a_kernel<<<dim3(NWC/4, NHC, TT*TT), 128, SMEM1A_BYTES>>>();
    stage1b_kernel<<<Q1/8, 256>>>();
    stage3_kernel<<<QF, 224>>>((float*)d_out);
}

// round 8
// speedup vs baseline: 1.4436x; 1.0189x over previous
#include <cuda_runtime.h>
#include <float.h>

#define TT   3
#define HH   192
#define WW   192
#define CC   64
#define HWSZ (HH*WW)
#define NHC  24
#define NWC  24
#define Q1   (TT*NHC*NWC)   // 1728
#define NHF  48
#define NWF  48
#define QF   (TT*NHF*NWF)   // 6912
#define KK   7
#define SS   192            // candidates per query

// scratch (static __device__ arrays — allowed; no runtime allocation)
__device__ float g_v0t[TT*HWSZ*CC];
__device__ float g_v1t[TT*HWSZ*CC];
__device__ float g_sd[Q1*SS];
__device__ int   g_inds[Q1*KK*3];

__device__ __forceinline__ int refl(int i, int L) {
    i = i < 0 ? -i : i;
    return (i >= L) ? (2*(L-1) - i) : i;
}

// rotate the ncu fixed capture slot onto stage1a (diagnostic)
__global__ void dummy_kernel() {}

// ---------------------------------------------------------------------------
// Transpose (T,C,H,W) -> (T,H,W,C), channels-last, for both videos.
// ---------------------------------------------------------------------------
__global__ void __launch_bounds__(256) transpose_kernel(const float* __restrict__ v0,
                                                        const float* __restrict__ v1) {
    const float* src = (blockIdx.z == 0) ? v0 : v1;
    float* dst       = (blockIdx.z == 0) ? g_v0t : g_v1t;
    const int t    = blockIdx.y;
    const int pix0 = blockIdx.x * 32;

    __shared__ float tile[CC][33];
    const int tx  = threadIdx.x & 31;
    const int grp = threadIdx.x >> 5;   // 0..7

    #pragma unroll
    for (int cc = 0; cc < CC; cc += 8) {
        int c = cc + grp;
        tile[c][tx] = src[((size_t)(t*CC + c))*HWSZ + pix0 + tx];
    }
    __syncthreads();
    #pragma unroll
    for (int i = 0; i < 8; ++i) {
        int idx = i*256 + threadIdx.x;        // 0..2047
        int pix = idx >> 6;                   // 0..31
        int ch  = idx & 63;
        dst[((size_t)t*HWSZ + pix0 + pix)*CC + ch] = tile[ch][pix];
    }
}

// ---------------------------------------------------------------------------
// Stage 1a v5: shared candidate window loaded ONCE per (qi,qj0,t) block;
// qt looped inside (query patches reloaded per qt).
// grid (6, 24, 3): block = (4 adjacent queries, row qi, t). 128 thr = 4 warps;
// warp u = query qj0+u. lane = dyi*4 + pair; thread owns candidates
// dxi = 2*pair, 2*pair+1.
// Per candidate, per offset (dri,ox): p = sequential fma chain over c=0..63,
// then acc += p in (dri major, ox ascending) order. DO NOT REORDER — this
// reproduces the reference's fp tie resolution bit-for-bit.
// ---------------------------------------------------------------------------
#define CSTR2   68                    // col-slot stride (floats)
#define ROWSTR2 (38*CSTR2 + 12)       // 2596 floats; conflict-free reads
#define SV_FLOATS (14*ROWSTR2)        // 36344
#define SQ_FLOATS (4*49*CC)           // 12544
#define SMEM1A_BYTES ((SV_FLOATS + SQ_FLOATS)*4)   // 195552 bytes

__global__ void __launch_bounds__(128) stage1a_kernel() {
    extern __shared__ float sv[];
    float* sq = sv + SV_FLOATS;

    const int qj0 = blockIdx.x * 4;
    const int qi  = blockIdx.y;
    const int t   = blockIdx.z;
    const int qh  = qi * 8;
    const int qw0 = qj0 * 8;

    const int tid  = threadIdx.x;
    const int u    = tid >> 5;        // query within block (warp id)
    const int lane = tid & 31;
    const int dyi  = lane >> 2;       // 0..7
    const int pair = lane & 3;        // 0..3 -> dxi {2p, 2p+1}

    // cooperative load: candidate window (ONCE per block)
    const float* v1base = g_v1t + (size_t)t*HWSZ*CC;
    for (int i = tid; i < 14*38*16; i += 128) {
        int r   = i / (38*16);
        int rem = i % (38*16);
        int s   = rem >> 4;
        int c4  = rem & 15;
        int y = refl(qh - 7 + r, HH);
        int x = refl(qw0 - 7 + s, WW);
        float4 v = reinterpret_cast<const float4*>(v1base + ((size_t)y*WW + x)*CC)[c4];
        *reinterpret_cast<float4*>(sv + r*ROWSTR2 + s*CSTR2 + c4*4) = v;
    }

    const float* svw = sv + (8*u + 2*pair)*CSTR2;

    for (int qt = 0; qt < TT; ++qt) {
        __syncthreads();   // window done (qt=0) / previous compute done (qt>0)

        // cooperative load: 4 query patches for this qt
        const float* v0base = g_v0t + (size_t)qt*HWSZ*CC;
        for (int i = tid; i < 4*49*16; i += 128) {
            int u2  = i / (49*16);
            int rem = i % (49*16);
            int o   = rem >> 4;
            int c4  = rem & 15;
            int y = refl(qh + (o/7) - 3, HH);
            int x = refl(qw0 + 8*u2 + (o%7) - 3, WW);
            float4 v = reinterpret_cast<const float4*>(v0base + ((size_t)y*WW + x)*CC)[c4];
            *reinterpret_cast<float4*>(sq + u2*(49*CC) + o*CC + c4*4) = v;
        }
        __syncthreads();

        const int q = qt*(NHC*NWC) + qi*NWC + (qj0 + u);
        const float* qbase = sq + u*(49*CC);

        float acc0 = 0.f, acc1 = 0.f;

        for (int dri = 0; dri < 7; ++dri) {
            const float* qrow = qbase + dri*7*CC;
            const float* vrow = svw + (dyi + dri)*ROWSTR2;

            float p0[7], p1[7];
            #pragma unroll
            for (int ox = 0; ox < 7; ++ox) { p0[ox] = 0.f; p1[ox] = 0.f; }

            #pragma unroll 2
            for (int c4 = 0; c4 < 16; ++c4) {
                float4 w[8];
                #pragma unroll
                for (int j = 0; j < 8; ++j)
                    w[j] = *reinterpret_cast<const float4*>(vrow + j*CSTR2 + c4*4);
                #pragma unroll
                for (int ox = 0; ox < 7; ++ox) {
                    float4 a  = *reinterpret_cast<const float4*>(qrow + ox*CC + c4*4);
                    float4 b0 = w[ox];      // candidate dxi = 2*pair
                    float4 b1 = w[ox + 1];  // candidate dxi = 2*pair + 1
                    p0[ox] = fmaf(a.x, b0.x, p0[ox]);
                    p0[ox] = fmaf(a.y, b0.y, p0[ox]);
                    p0[ox] = fmaf(a.z, b0.z, p0[ox]);
                    p0[ox] = fmaf(a.w, b0.w, p0[ox]);
                    p1[ox] = fmaf(a.x, b1.x, p1[ox]);
                    p1[ox] = fmaf(a.y, b1.y, p1[ox]);
                    p1[ox] = fmaf(a.z, b1.z, p1[ox]);
                    p1[ox] = fmaf(a.w, b1.w, p1[ox]);
                }
            }
            #pragma unroll
            for (int ox = 0; ox < 7; ++ox) { acc0 += p0[ox]; acc1 += p1[ox]; }
        }

        float2 res = make_float2(acc0, acc1);
        *reinterpret_cast<float2*>(&g_sd[q*SS + t*64 + dyi*8 + 2*pair]) = res;
    }
}

// ---------------------------------------------------------------------------
// Stage 1b: warp-per-query top-7 via shuffles (no block syncs).
// Stable: ties -> lowest candidate index (lax.top_k semantics).
// ---------------------------------------------------------------------------
__global__ void __launch_bounds__(256) stage1b_kernel() {
    const int lane = threadIdx.x & 31;
    const int q = blockIdx.x*8 + (threadIdx.x >> 5);
    const int rr = q % (NHC*NWC);
    const int qh = (rr / NWC) * 8;
    const int qw = (rr % NWC) * 8;

    float v[6];
    #pragma unroll
    for (int j = 0; j < 6; ++j) v[j] = g_sd[q*SS + j*32 + lane];

    #pragma unroll 1
    for (int k = 0; k < KK; ++k) {
        float bv = v[0]; int bi = lane;
        #pragma unroll
        for (int j = 1; j < 6; ++j) {
            if (v[j] > bv) { bv = v[j]; bi = j*32 + lane; }
        }
        #pragma unroll
        for (int s = 16; s > 0; s >>= 1) {
            float ov = __shfl_xor_sync(0xffffffffu, bv, s);
            int   oi = __shfl_xor_sync(0xffffffffu, bi, s);
            if (ov > bv || (ov == bv && oi < bi)) { bv = ov; bi = oi; }
        }
        if (lane == 0) {
            int base = (q*KK + k)*3;
            g_inds[base + 0] = bi >> 6;                   // ct
            g_inds[base + 1] = qh + ((bi >> 3) & 7) - 4;  // ch (raw)
            g_inds[base + 2] = qw + (bi & 7) - 4;         // cw (raw)
        }
        if ((bi & 31) == lane) {
            int jj = bi >> 5;
            #pragma unroll
            for (int j = 0; j < 6; ++j) if (j == jj) v[j] = -FLT_MAX;
        }
    }
}

// ---------------------------------------------------------------------------
// Stage 2+3 fused v4: float4 patch load, element-scaled offset table.
// block = 224 threads (7 warps) per fine query; warp k handles candidate k.
// ---------------------------------------------------------------------------
__global__ void __launch_bounds__(224) stage3_kernel(float* __restrict__ out) {
    const int q  = blockIdx.x;
    const int ft = q / (NHF*NWF);
    const int rr = q % (NHF*NWF);
    const int fi = rr / NWF, fj = rr % NWF;
    const int fh = fi*4, fw = fj*4;

    __shared__ float sp[49*CC];
    __shared__ int   scand[KK*3];
    __shared__ int   soff[KK*49];

    const int tid = threadIdx.x;
    // query patch, vectorized
    for (int i = tid; i < 49*16; i += 224) {
        int o = i >> 4, c4 = i & 15;
        int y = refl(fh + (o/7) - 3, HH);
        int x = refl(fw + (o%7) - 3, WW);
        reinterpret_cast<float4*>(sp)[i] =
            reinterpret_cast<const float4*>(g_v0t + ((size_t)ft*HWSZ + (size_t)y*WW + x)*CC)[c4];
    }
    if (tid < KK) {
        int it, ih, iw;
        if (tid == 0) { it = ft; ih = fh; iw = fw; }
        else {
            int ci = min(fi >> 1, NHC - 1);
            int cj = min(fj >> 1, NWC - 1);
            int qlin = ft*NHC*NWC + ci*NWC + cj;
            int b = (qlin*KK + tid)*3;
            it = g_inds[b + 0];
            ih = refl(g_inds[b + 1] + (fh - ci*8), HH);
            iw = refl(g_inds[b + 2] + (fw - cj*8), WW);
        }
        scand[tid*3 + 0] = it;
        scand[tid*3 + 1] = ih;
        scand[tid*3 + 2] = iw;
        // inds_f (as float), laid out after dists_f
        size_t ob = (size_t)QF*KK + ((size_t)q*KK + tid)*3;
        out[ob + 0] = (float)it;
        out[ob + 1] = (float)ih;
        out[ob + 2] = (float)iw;
    }
    __syncthreads();

    // cooperative offset table: soff[k][o] = (y1*W + x1)*CC (element offset)
    for (int i = tid; i < KK*49; i += 224) {
        int k = i / 49, o = i % 49;
        int y1 = refl(scand[k*3 + 1] + o/7 - 3, HH);
        int x1 = refl(scand[k*3 + 2] + o%7 - 3, WW);
        soff[i] = (y1*WW + x1)*CC;
    }
    __syncthreads();

    const int warp = tid >> 5;
    const int lane = tid & 31;
    const int it = scand[warp*3 + 0];
    const float* v1b = g_v1t + (size_t)it*HWSZ*CC + 2*lane;
    const int* mysoff = soff + warp*49;
    const float* spl = sp + 2*lane;

    float2 acc = make_float2(0.f, 0.f);
    #pragma unroll 7
    for (int o = 0; o < 49; ++o) {
        float2 wv = *reinterpret_cast<const float2*>(v1b + mysoff[o]);
        float2 pv = *reinterpret_cast<const float2*>(spl + o*CC);
        acc.x = fmaf(pv.x, wv.x, acc.x);
        acc.y = fmaf(pv.y, wv.y, acc.y);
    }
    float v = acc.x + acc.y;
    #pragma unroll
    for (int s = 16; s > 0; s >>= 1)
        v += __shfl_down_sync(0xffffffffu, v, s);
    if (lane == 0)
        out[(size_t)q*KK + warp] = v;
}

// ---------------------------------------------------------------------------
extern "C" void kernel_launch(void* const* d_in, const int* in_sizes, int n_in,
                              void* d_out, int out_size) {
    const float* vid0 = (const float*)d_in[0];
    const float* vid1 = (const float*)d_in[1];
    // d_in[2] = flows, unused by the reference

    cudaFuncSetAttribute(stage1a_kernel,
                         cudaFuncAttributeMaxDynamicSharedMemorySize, SMEM1A_BYTES);

    // two dummies rotate the ncu fixed capture slot from stage3 onto stage1a
    dummy_kernel<<<1, 32>>>();
    dummy_kernel<<<1, 32>>>();

    dim3 tgrid(HWSZ/32, TT, 2);
    transpose_kernel<<<tgrid, 256>>>(vid0, vid1);
    stage1a_kernel<<<dim3(NWC/4, NHC, TT), 128, SMEM1A_BYTES>>>();
    stage1b_kernel<<<Q1/8, 256>>>();
    stage3_kernel<<<QF, 224>>>((float*)d_out);
}

// round 9
// speedup vs baseline: 1.6062x; 1.1127x over previous
#include <cuda_runtime.h>
#include <float.h>

#define TT   3
#define HH   192
#define WW   192
#define CC   64
#define HWSZ (HH*WW)
#define NHC  24
#define NWC  24
#define Q1   (TT*NHC*NWC)   // 1728
#define NHF  48
#define NWF  48
#define QF   (TT*NHF*NWF)   // 6912
#define KK   7
#define SS   192            // candidates per query

// scratch (static __device__ arrays — allowed; no runtime allocation)
__device__ float g_v0t[TT*HWSZ*CC];
__device__ float g_v1t[TT*HWSZ*CC];
__device__ float g_sd[Q1*SS];
__device__ int   g_inds[Q1*KK*3];

__device__ __forceinline__ int refl(int i, int L) {
    i = i < 0 ? -i : i;
    return (i >= L) ? (2*(L-1) - i) : i;
}

// rotate the ncu fixed capture slot onto stage1a (diagnostic)
__global__ void dummy_kernel() {}

// ---------------------------------------------------------------------------
// Transpose (T,C,H,W) -> (T,H,W,C), channels-last, for both videos.
// ---------------------------------------------------------------------------
__global__ void __launch_bounds__(256) transpose_kernel(const float* __restrict__ v0,
                                                        const float* __restrict__ v1) {
    const float* src = (blockIdx.z == 0) ? v0 : v1;
    float* dst       = (blockIdx.z == 0) ? g_v0t : g_v1t;
    const int t    = blockIdx.y;
    const int pix0 = blockIdx.x * 32;

    __shared__ float tile[CC][33];
    const int tx  = threadIdx.x & 31;
    const int grp = threadIdx.x >> 5;   // 0..7

    #pragma unroll
    for (int cc = 0; cc < CC; cc += 8) {
        int c = cc + grp;
        tile[c][tx] = src[((size_t)(t*CC + c))*HWSZ + pix0 + tx];
    }
    __syncthreads();
    #pragma unroll
    for (int i = 0; i < 8; ++i) {
        int idx = i*256 + threadIdx.x;        // 0..2047
        int pix = idx >> 6;                   // 0..31
        int ch  = idx & 63;
        dst[((size_t)t*HWSZ + pix0 + pix)*CC + ch] = tile[ch][pix];
    }
}

// ---------------------------------------------------------------------------
// Stage 1a v6: qt folded into warps for 3x occupancy.
// grid (6, 24, 3): block = (4 adjacent queries, row qi, t). 384 thr = 12 warps;
// warp = (qt, u): qt = wid>>2, u = wid&3 (query qj0+u).
// lane = dyi*4 + pair; thread owns candidates dxi = 2*pair, 2*pair+1.
// Candidate window (depends on t only) in smem, loaded once.
// Query-patch values read via warp-uniform LDG.128 (L1-resident) — same
// values as before, so bit-exactness is preserved.
// Per candidate, per offset (dri,ox): p = sequential fma chain over c=0..63,
// then acc += p in (dri major, ox ascending) order. DO NOT REORDER — this
// reproduces the reference's fp tie resolution bit-for-bit.
// ---------------------------------------------------------------------------
#define CSTR2   68                    // col-slot stride (floats)
#define ROWSTR2 (38*CSTR2 + 12)       // 2596 floats; conflict-free reads
#define SV_BYTES (14*ROWSTR2*4)       // 145376 bytes dynamic smem

__global__ void __launch_bounds__(384) stage1a_kernel() {
    extern __shared__ float sv[];

    const int qj0 = blockIdx.x * 4;
    const int qi  = blockIdx.y;
    const int t   = blockIdx.z;
    const int qh  = qi * 8;
    const int qw0 = qj0 * 8;

    const int tid  = threadIdx.x;
    const int wid  = tid >> 5;        // 0..11
    const int qt   = wid >> 2;        // 0..2
    const int u    = wid & 3;         // query within block
    const int lane = tid & 31;
    const int dyi  = lane >> 2;       // 0..7
    const int pair = lane & 3;        // 0..3 -> dxi {2p, 2p+1}

    // cooperative load: candidate window (once)
    const float* v1base = g_v1t + (size_t)t*HWSZ*CC;
    for (int i = tid; i < 14*38*16; i += 384) {
        int r   = i / (38*16);
        int rem = i % (38*16);
        int s   = rem >> 4;
        int c4  = rem & 15;
        int y = refl(qh - 7 + r, HH);
        int x = refl(qw0 - 7 + s, WW);
        float4 v = reinterpret_cast<const float4*>(v1base + ((size_t)y*WW + x)*CC)[c4];
        *reinterpret_cast<float4*>(sv + r*ROWSTR2 + s*CSTR2 + c4*4) = v;
    }
    __syncthreads();

    const int q  = qt*(NHC*NWC) + qi*NWC + (qj0 + u);
    const int qw = qw0 + u*8;

    // query patch col element-offsets (uniform within warp)
    int xq[7];
    #pragma unroll
    for (int ox = 0; ox < 7; ++ox) xq[ox] = refl(qw + ox - 3, WW) * CC;
    const float* v0base = g_v0t + (size_t)qt*HWSZ*CC;

    float acc0 = 0.f, acc1 = 0.f;
    const float* svw = sv + (8*u + 2*pair)*CSTR2;

    for (int dri = 0; dri < 7; ++dri) {
        const int yq = refl(qh + dri - 3, HH);
        const float* qrow = v0base + (size_t)yq*WW*CC;
        const float* vrow = svw + (dyi + dri)*ROWSTR2;

        float p0[7], p1[7];
        #pragma unroll
        for (int ox = 0; ox < 7; ++ox) { p0[ox] = 0.f; p1[ox] = 0.f; }

        #pragma unroll 2
        for (int c4 = 0; c4 < 16; ++c4) {
            float4 a[7];
            #pragma unroll
            for (int ox = 0; ox < 7; ++ox)
                a[ox] = *reinterpret_cast<const float4*>(qrow + xq[ox] + c4*4);
            float4 w[8];
            #pragma unroll
            for (int j = 0; j < 8; ++j)
                w[j] = *reinterpret_cast<const float4*>(vrow + j*CSTR2 + c4*4);
            #pragma unroll
            for (int ox = 0; ox < 7; ++ox) {
                float4 b0 = w[ox];      // candidate dxi = 2*pair
                float4 b1 = w[ox + 1];  // candidate dxi = 2*pair + 1
                p0[ox] = fmaf(a[ox].x, b0.x, p0[ox]);
                p0[ox] = fmaf(a[ox].y, b0.y, p0[ox]);
                p0[ox] = fmaf(a[ox].z, b0.z, p0[ox]);
                p0[ox] = fmaf(a[ox].w, b0.w, p0[ox]);
                p1[ox] = fmaf(a[ox].x, b1.x, p1[ox]);
                p1[ox] = fmaf(a[ox].y, b1.y, p1[ox]);
                p1[ox] = fmaf(a[ox].z, b1.z, p1[ox]);
                p1[ox] = fmaf(a[ox].w, b1.w, p1[ox]);
            }
        }
        #pragma unroll
        for (int ox = 0; ox < 7; ++ox) { acc0 += p0[ox]; acc1 += p1[ox]; }
    }

    float2 res = make_float2(acc0, acc1);
    *reinterpret_cast<float2*>(&g_sd[q*SS + t*64 + dyi*8 + 2*pair]) = res;
}

// ---------------------------------------------------------------------------
// Stage 1b: warp-per-query top-7 via shuffles (no block syncs).
// Stable: ties -> lowest candidate index (lax.top_k semantics).
// ---------------------------------------------------------------------------
__global__ void __launch_bounds__(256) stage1b_kernel() {
    const int lane = threadIdx.x & 31;
    const int q = blockIdx.x*8 + (threadIdx.x >> 5);
    const int rr = q % (NHC*NWC);
    const int qh = (rr / NWC) * 8;
    const int qw = (rr % NWC) * 8;

    float v[6];
    #pragma unroll
    for (int j = 0; j < 6; ++j) v[j] = g_sd[q*SS + j*32 + lane];

    #pragma unroll 1
    for (int k = 0; k < KK; ++k) {
        float bv = v[0]; int bi = lane;
        #pragma unroll
        for (int j = 1; j < 6; ++j) {
            if (v[j] > bv) { bv = v[j]; bi = j*32 + lane; }
        }
        #pragma unroll
        for (int s = 16; s > 0; s >>= 1) {
            float ov = __shfl_xor_sync(0xffffffffu, bv, s);
            int   oi = __shfl_xor_sync(0xffffffffu, bi, s);
            if (ov > bv || (ov == bv && oi < bi)) { bv = ov; bi = oi; }
        }
        if (lane == 0) {
            int base = (q*KK + k)*3;
            g_inds[base + 0] = bi >> 6;                   // ct
            g_inds[base + 1] = qh + ((bi >> 3) & 7) - 4;  // ch (raw)
            g_inds[base + 2] = qw + (bi & 7) - 4;         // cw (raw)
        }
        if ((bi & 31) == lane) {
            int jj = bi >> 5;
            #pragma unroll
            for (int j = 0; j < 6; ++j) if (j == jj) v[j] = -FLT_MAX;
        }
    }
}

// ---------------------------------------------------------------------------
// Stage 2+3 fused: float4 patch load, element-scaled offset table.
// block = 224 threads (7 warps) per fine query; warp k handles candidate k.
// ---------------------------------------------------------------------------
__global__ void __launch_bounds__(224) stage3_kernel(float* __restrict__ out) {
    const int q  = blockIdx.x;
    const int ft = q / (NHF*NWF);
    const int rr = q % (NHF*NWF);
    const int fi = rr / NWF, fj = rr % NWF;
    const int fh = fi*4, fw = fj*4;

    __shared__ float sp[49*CC];
    __shared__ int   scand[KK*3];
    __shared__ int   soff[KK*49];

    const int tid = threadIdx.x;
    // query patch, vectorized
    for (int i = tid; i < 49*16; i += 224) {
        int o = i >> 4, c4 = i & 15;
        int y = refl(fh + (o/7) - 3, HH);
        int x = refl(fw + (o%7) - 3, WW);
        reinterpret_cast<float4*>(sp)[i] =
            reinterpret_cast<const float4*>(g_v0t + ((size_t)ft*HWSZ + (size_t)y*WW + x)*CC)[c4];
    }
    if (tid < KK) {
        int it, ih, iw;
        if (tid == 0) { it = ft; ih = fh; iw = fw; }
        else {
            int ci = min(fi >> 1, NHC - 1);
            int cj = min(fj >> 1, NWC - 1);
            int qlin = ft*NHC*NWC + ci*NWC + cj;
            int b = (qlin*KK + tid)*3;
            it = g_inds[b + 0];
            ih = refl(g_inds[b + 1] + (fh - ci*8), HH);
            iw = refl(g_inds[b + 2] + (fw - cj*8), WW);
        }
        scand[tid*3 + 0] = it;
        scand[tid*3 + 1] = ih;
        scand[tid*3 + 2] = iw;
        // inds_f (as float), laid out after dists_f
        size_t ob = (size_t)QF*KK + ((size_t)q*KK + tid)*3;
        out[ob + 0] = (float)it;
        out[ob + 1] = (float)ih;
        out[ob + 2] = (float)iw;
    }
    __syncthreads();

    // cooperative offset table: soff[k][o] = (y1*W + x1)*CC (element offset)
    for (int i = tid; i < KK*49; i += 224) {
        int k = i / 49, o = i % 49;
        int y1 = refl(scand[k*3 + 1] + o/7 - 3, HH);
        int x1 = refl(scand[k*3 + 2] + o%7 - 3, WW);
        soff[i] = (y1*WW + x1)*CC;
    }
    __syncthreads();

    const int warp = tid >> 5;
    const int lane = tid & 31;
    const int it = scand[warp*3 + 0];
    const float* v1b = g_v1t + (size_t)it*HWSZ*CC + 2*lane;
    const int* mysoff = soff + warp*49;
    const float* spl = sp + 2*lane;

    float2 acc = make_float2(0.f, 0.f);
    #pragma unroll 7
    for (int o = 0; o < 49; ++o) {
        float2 wv = *reinterpret_cast<const float2*>(v1b + mysoff[o]);
        float2 pv = *reinterpret_cast<const float2*>(spl + o*CC);
        acc.x = fmaf(pv.x, wv.x, acc.x);
        acc.y = fmaf(pv.y, wv.y, acc.y);
    }
    float v = acc.x + acc.y;
    #pragma unroll
    for (int s = 16; s > 0; s >>= 1)
        v += __shfl_down_sync(0xffffffffu, v, s);
    if (lane == 0)
        out[(size_t)q*KK + warp] = v;
}

// ---------------------------------------------------------------------------
extern "C" void kernel_launch(void* const* d_in, const int* in_sizes, int n_in,
                              void* d_out, int out_size) {
    const float* vid0 = (const float*)d_in[0];
    const float* vid1 = (const float*)d_in[1];
    // d_in[2] = flows, unused by the reference

    cudaFuncSetAttribute(stage1a_kernel,
                         cudaFuncAttributeMaxDynamicSharedMemorySize, SV_BYTES);

    // two dummies keep the ncu fixed capture slot on stage1a
    dummy_kernel<<<1, 32>>>();
    dummy_kernel<<<1, 32>>>();

    dim3 tgrid(HWSZ/32, TT, 2);
    transpose_kernel<<<tgrid, 256>>>(vid0, vid1);
    stage1a_kernel<<<dim3(NWC/4, NHC, TT), 384, SV_BYTES>>>();
    stage1b_kernel<<<Q1/8, 256>>>();
    stage3_kernel<<<QF, 224>>>((float*)d_out);
}

// round 10
// speedup vs baseline: 1.9554x; 1.2174x over previous
#include <cuda_runtime.h>
#include <float.h>

#define TT   3
#define HH   192
#define WW   192
#define CC   64
#define HWSZ (HH*WW)
#define NHC  24
#define NWC  24
#define Q1   (TT*NHC*NWC)   // 1728
#define NHF  48
#define NWF  48
#define QF   (TT*NHF*NWF)   // 6912
#define KK   7
#define SS   192            // candidates per query

// scratch (static __device__ arrays — allowed; no runtime allocation)
__device__ float g_v0t[TT*HWSZ*CC];
__device__ float g_v1t[TT*HWSZ*CC];
__device__ float g_sd[Q1*SS];
__device__ int   g_inds[Q1*KK*3];

__device__ __forceinline__ int refl(int i, int L) {
    i = i < 0 ? -i : i;
    return (i >= L) ? (2*(L-1) - i) : i;
}

// rotate the ncu fixed capture slot onto stage1a (diagnostic)
__global__ void dummy_kernel() {}

// ---------------------------------------------------------------------------
// Transpose (T,C,H,W) -> (T,H,W,C), channels-last, for both videos.
// ---------------------------------------------------------------------------
__global__ void __launch_bounds__(256) transpose_kernel(const float* __restrict__ v0,
                                                        const float* __restrict__ v1) {
    const float* src = (blockIdx.z == 0) ? v0 : v1;
    float* dst       = (blockIdx.z == 0) ? g_v0t : g_v1t;
    const int t    = blockIdx.y;
    const int pix0 = blockIdx.x * 32;

    __shared__ float tile[CC][33];
    const int tx  = threadIdx.x & 31;
    const int grp = threadIdx.x >> 5;   // 0..7

    #pragma unroll
    for (int cc = 0; cc < CC; cc += 8) {
        int c = cc + grp;
        tile[c][tx] = src[((size_t)(t*CC + c))*HWSZ + pix0 + tx];
    }
    __syncthreads();
    #pragma unroll
    for (int i = 0; i < 8; ++i) {
        int idx = i*256 + threadIdx.x;        // 0..2047
        int pix = idx >> 6;                   // 0..31
        int ch  = idx & 63;
        dst[((size_t)t*HWSZ + pix0 + pix)*CC + ch] = tile[ch][pix];
    }
}

// ---------------------------------------------------------------------------
// Stage 1a v7: explicit software-pipelined inner loop (double-buffered
// register prefetch) on top of the v6 structure.
// grid (6, 24, 3): block = (4 adjacent queries, row qi, t). 384 thr = 12 warps;
// warp = (qt, u). lane = dyi*4 + pair; thread owns candidates dxi = 2p, 2p+1.
// Candidate window (depends on t only) in smem; query-patch via warp-uniform
// LDG.128. Per candidate, per offset (dri,ox): p = sequential fma chain over
// c = 0..63, then acc += p in (dri major, ox ascending) order. DO NOT REORDER
// the arithmetic — it reproduces the reference's fp tie resolution
// bit-for-bit. (Prefetching only reorders LOADS, which is value-safe.)
// ---------------------------------------------------------------------------
#define CSTR2   68                    // col-slot stride (floats)
#define ROWSTR2 (38*CSTR2 + 12)       // 2596 floats; conflict-free reads
#define SV_BYTES (14*ROWSTR2*4)       // 145376 bytes dynamic smem

#define LOAD_WA(wb, ab, c4)                                                   \
    do {                                                                      \
        _Pragma("unroll")                                                     \
        for (int j = 0; j < 8; ++j)                                           \
            wb[j] = *reinterpret_cast<const float4*>(vrow + j*CSTR2 + (c4)*4);\
        _Pragma("unroll")                                                     \
        for (int ox = 0; ox < 7; ++ox)                                        \
            ab[ox] = *reinterpret_cast<const float4*>(qrow + xq[ox] + (c4)*4);\
    } while (0)

#define COMPUTE_WA(wb, ab)                                                    \
    do {                                                                      \
        _Pragma("unroll")                                                     \
        for (int ox = 0; ox < 7; ++ox) {                                      \
            float4 b0 = wb[ox];                                               \
            float4 b1 = wb[ox + 1];                                           \
            p0[ox] = fmaf(ab[ox].x, b0.x, p0[ox]);                            \
            p0[ox] = fmaf(ab[ox].y, b0.y, p0[ox]);                            \
            p0[ox] = fmaf(ab[ox].z, b0.z, p0[ox]);                            \
            p0[ox] = fmaf(ab[ox].w, b0.w, p0[ox]);                            \
            p1[ox] = fmaf(ab[ox].x, b1.x, p1[ox]);                            \
            p1[ox] = fmaf(ab[ox].y, b1.y, p1[ox]);                            \
            p1[ox] = fmaf(ab[ox].z, b1.z, p1[ox]);                            \
            p1[ox] = fmaf(ab[ox].w, b1.w, p1[ox]);                            \
        }                                                                     \
    } while (0)

__global__ void __launch_bounds__(384, 1) stage1a_kernel() {
    extern __shared__ float sv[];

    const int qj0 = blockIdx.x * 4;
    const int qi  = blockIdx.y;
    const int t   = blockIdx.z;
    const int qh  = qi * 8;
    const int qw0 = qj0 * 8;

    const int tid  = threadIdx.x;
    const int wid  = tid >> 5;        // 0..11
    const int qt   = wid >> 2;        // 0..2
    const int u    = wid & 3;         // query within block
    const int lane = tid & 31;
    const int dyi  = lane >> 2;       // 0..7
    const int pair = lane & 3;        // 0..3 -> dxi {2p, 2p+1}

    // cooperative load: candidate window (once)
    const float* v1base = g_v1t + (size_t)t*HWSZ*CC;
    for (int i = tid; i < 14*38*16; i += 384) {
        int r   = i / (38*16);
        int rem = i % (38*16);
        int s   = rem >> 4;
        int c4  = rem & 15;
        int y = refl(qh - 7 + r, HH);
        int x = refl(qw0 - 7 + s, WW);
        float4 v = reinterpret_cast<const float4*>(v1base + ((size_t)y*WW + x)*CC)[c4];
        *reinterpret_cast<float4*>(sv + r*ROWSTR2 + s*CSTR2 + c4*4) = v;
    }
    __syncthreads();

    const int q  = qt*(NHC*NWC) + qi*NWC + (qj0 + u);
    const int qw = qw0 + u*8;

    // query patch col element-offsets (uniform within warp)
    int xq[7];
    #pragma unroll
    for (int ox = 0; ox < 7; ++ox) xq[ox] = refl(qw + ox - 3, WW) * CC;
    const float* v0base = g_v0t + (size_t)qt*HWSZ*CC;

    float acc0 = 0.f, acc1 = 0.f;
    const float* svw = sv + (8*u + 2*pair)*CSTR2;

    for (int dri = 0; dri < 7; ++dri) {
        const int yq = refl(qh + dri - 3, HH);
        const float* qrow = v0base + (size_t)yq*WW*CC;
        const float* vrow = svw + (dyi + dri)*ROWSTR2;

        float p0[7], p1[7];
        #pragma unroll
        for (int ox = 0; ox < 7; ++ox) { p0[ox] = 0.f; p1[ox] = 0.f; }

        // software pipeline: prefetch one c4-iter ahead into alternating bufs
        float4 w0[8], a0[7], w1[8], a1[7];
        LOAD_WA(w0, a0, 0);
        #pragma unroll
        for (int c4 = 0; c4 < 16; c4 += 2) {
            LOAD_WA(w1, a1, c4 + 1);     // prefetch c4+1
            COMPUTE_WA(w0, a0);          // compute c4
            if (c4 + 2 < 16)
                LOAD_WA(w0, a0, c4 + 2); // prefetch c4+2
            COMPUTE_WA(w1, a1);          // compute c4+1
        }
        #pragma unroll
        for (int ox = 0; ox < 7; ++ox) { acc0 += p0[ox]; acc1 += p1[ox]; }
    }

    float2 res = make_float2(acc0, acc1);
    *reinterpret_cast<float2*>(&g_sd[q*SS + t*64 + dyi*8 + 2*pair]) = res;
}

// ---------------------------------------------------------------------------
// Stage 1b: warp-per-query top-7 via shuffles (no block syncs).
// Stable: ties -> lowest candidate index (lax.top_k semantics).
// ---------------------------------------------------------------------------
__global__ void __launch_bounds__(256) stage1b_kernel() {
    const int lane = threadIdx.x & 31;
    const int q = blockIdx.x*8 + (threadIdx.x >> 5);
    const int rr = q % (NHC*NWC);
    const int qh = (rr / NWC) * 8;
    const int qw = (rr % NWC) * 8;

    float v[6];
    #pragma unroll
    for (int j = 0; j < 6; ++j) v[j] = g_sd[q*SS + j*32 + lane];

    #pragma unroll 1
    for (int k = 0; k < KK; ++k) {
        float bv = v[0]; int bi = lane;
        #pragma unroll
        for (int j = 1; j < 6; ++j) {
            if (v[j] > bv) { bv = v[j]; bi = j*32 + lane; }
        }
        #pragma unroll
        for (int s = 16; s > 0; s >>= 1) {
            float ov = __shfl_xor_sync(0xffffffffu, bv, s);
            int   oi = __shfl_xor_sync(0xffffffffu, bi, s);
            if (ov > bv || (ov == bv && oi < bi)) { bv = ov; bi = oi; }
        }
        if (lane == 0) {
            int base = (q*KK + k)*3;
            g_inds[base + 0] = bi >> 6;                   // ct
            g_inds[base + 1] = qh + ((bi >> 3) & 7) - 4;  // ch (raw)
            g_inds[base + 2] = qw + (bi & 7) - 4;         // cw (raw)
        }
        if ((bi & 31) == lane) {
            int jj = bi >> 5;
            #pragma unroll
            for (int j = 0; j < 6; ++j) if (j == jj) v[j] = -FLT_MAX;
        }
    }
}

// ---------------------------------------------------------------------------
// Stage 2+3 fused: float4 patch load, element-scaled offset table.
// block = 224 threads (7 warps) per fine query; warp k handles candidate k.
// ---------------------------------------------------------------------------
__global__ void __launch_bounds__(224) stage3_kernel(float* __restrict__ out) {
    const int q  = blockIdx.x;
    const int ft = q / (NHF*NWF);
    const int rr = q % (NHF*NWF);
    const int fi = rr / NWF, fj = rr % NWF;
    const int fh = fi*4, fw = fj*4;

    __shared__ float sp[49*CC];
    __shared__ int   scand[KK*3];
    __shared__ int   soff[KK*49];

    const int tid = threadIdx.x;
    // query patch, vectorized
    for (int i = tid; i < 49*16; i += 224) {
        int o = i >> 4, c4 = i & 15;
        int y = refl(fh + (o/7) - 3, HH);
        int x = refl(fw + (o%7) - 3, WW);
        reinterpret_cast<float4*>(sp)[i] =
            reinterpret_cast<const float4*>(g_v0t + ((size_t)ft*HWSZ + (size_t)y*WW + x)*CC)[c4];
    }
    if (tid < KK) {
        int it, ih, iw;
        if (tid == 0) { it = ft; ih = fh; iw = fw; }
        else {
            int ci = min(fi >> 1, NHC - 1);
            int cj = min(fj >> 1, NWC - 1);
            int qlin = ft*NHC*NWC + ci*NWC + cj;
            int b = (qlin*KK + tid)*3;
            it = g_inds[b + 0];
            ih = refl(g_inds[b + 1] + (fh - ci*8), HH);
            iw = refl(g_inds[b + 2] + (fw - cj*8), WW);
        }
        scand[tid*3 + 0] = it;
        scand[tid*3 + 1] = ih;
        scand[tid*3 + 2] = iw;
        // inds_f (as float), laid out after dists_f
        size_t ob = (size_t)QF*KK + ((size_t)q*KK + tid)*3;
        out[ob + 0] = (float)it;
        out[ob + 1] = (float)ih;
        out[ob + 2] = (float)iw;
    }
    __syncthreads();

    // cooperative offset table: soff[k][o] = (y1*W + x1)*CC (element offset)
    for (int i = tid; i < KK*49; i += 224) {
        int k = i / 49, o = i % 49;
        int y1 = refl(scand[k*3 + 1] + o/7 - 3, HH);
        int x1 = refl(scand[k*3 + 2] + o%7 - 3, WW);
        soff[i] = (y1*WW + x1)*CC;
    }
    __syncthreads();

    const int warp = tid >> 5;
    const int lane = tid & 31;
    const int it = scand[warp*3 + 0];
    const float* v1b = g_v1t + (size_t)it*HWSZ*CC + 2*lane;
    const int* mysoff = soff + warp*49;
    const float* spl = sp + 2*lane;

    float2 acc = make_float2(0.f, 0.f);
    #pragma unroll 7
    for (int o = 0; o < 49; ++o) {
        float2 wv = *reinterpret_cast<const float2*>(v1b + mysoff[o]);
        float2 pv = *reinterpret_cast<const float2*>(spl + o*CC);
        acc.x = fmaf(pv.x, wv.x, acc.x);
        acc.y = fmaf(pv.y, wv.y, acc.y);
    }
    float v = acc.x + acc.y;
    #pragma unroll
    for (int s = 16; s > 0; s >>= 1)
        v += __shfl_down_sync(0xffffffffu, v, s);
    if (lane == 0)
        out[(size_t)q*KK + warp] = v;
}

// ---------------------------------------------------------------------------
extern "C" void kernel_launch(void* const* d_in, const int* in_sizes, int n_in,
                              void* d_out, int out_size) {
    const float* vid0 = (const float*)d_in[0];
    const float* vid1 = (const float*)d_in[1];
    // d_in[2] = flows, unused by the reference

    cudaFuncSetAttribute(stage1a_kernel,
                         cudaFuncAttributeMaxDynamicSharedMemorySize, SV_BYTES);

    // two dummies keep the ncu fixed capture slot on stage1a
    dummy_kernel<<<1, 32>>>();
    dummy_kernel<<<1, 32>>>();

    dim3 tgrid(HWSZ/32, TT, 2);
    transpose_kernel<<<tgrid, 256>>>(vid0, vid1);
    stage1a_kernel<<<dim3(NWC/4, NHC, TT), 384, SV_BYTES>>>();
    stage1b_kernel<<<Q1/8, 256>>>();
    stage3_kernel<<<QF, 224>>>((float*)d_out);
}

// round 11
// speedup vs baseline: 2.4480x; 1.2519x over previous
#include <cuda_runtime.h>
#include <float.h>

#define TT   3
#define HH   192
#define WW   192
#define CC   64
#define HWSZ (HH*WW)
#define NHC  24
#define NWC  24
#define Q1   (TT*NHC*NWC)   // 1728
#define NHF  48
#define NWF  48
#define QF   (TT*NHF*NWF)   // 6912
#define KK   7
#define SS   192            // candidates per query

// scratch (static __device__ arrays — allowed; no runtime allocation)
__device__ float g_v0t[TT*HWSZ*CC];
__device__ float g_v1t[TT*HWSZ*CC];
__device__ float g_sd[Q1*SS];
__device__ int   g_inds[Q1*KK*3];

__device__ __forceinline__ int refl(int i, int L) {
    i = i < 0 ? -i : i;
    return (i >= L) ? (2*(L-1) - i) : i;
}

// rotate the ncu fixed capture slot onto stage1a (diagnostic)
__global__ void dummy_kernel() {}

// ---------------------------------------------------------------------------
// Transpose (T,C,H,W) -> (T,H,W,C), channels-last, for both videos.
// ---------------------------------------------------------------------------
__global__ void __launch_bounds__(256) transpose_kernel(const float* __restrict__ v0,
                                                        const float* __restrict__ v1) {
    const float* src = (blockIdx.z == 0) ? v0 : v1;
    float* dst       = (blockIdx.z == 0) ? g_v0t : g_v1t;
    const int t    = blockIdx.y;
    const int pix0 = blockIdx.x * 32;

    __shared__ float tile[CC][33];
    const int tx  = threadIdx.x & 31;
    const int grp = threadIdx.x >> 5;   // 0..7

    #pragma unroll
    for (int cc = 0; cc < CC; cc += 8) {
        int c = cc + grp;
        tile[c][tx] = src[((size_t)(t*CC + c))*HWSZ + pix0 + tx];
    }
    __syncthreads();
    #pragma unroll
    for (int i = 0; i < 8; ++i) {
        int idx = i*256 + threadIdx.x;        // 0..2047
        int pix = idx >> 6;                   // 0..31
        int ch  = idx & 63;
        dst[((size_t)t*HWSZ + pix0 + pix)*CC + ch] = tile[ch][pix];
    }
}

// ---------------------------------------------------------------------------
// Stage 1a v8: QUAD candidate packing + software-pipelined inner loop.
// grid (6, 24, 3): block = (4 adjacent queries, row qi, t). 192 thr = 6 warps.
// query-slot = tid>>4 (0..11): qt = slot>>2, u = slot&3.
// within slot: sub = tid&15; dyi = sub>>1, quad = sub&1; thread owns
// candidates dxi = 4*quad .. 4*quad+3 (4 chains -> 28 FMA4 per 17 loads).
// Candidate window (depends on t only) in smem; query-patch via slot-uniform
// LDG.128. Per candidate, per offset (dri,ox): p = sequential fma chain over
// c = 0..63, then acc += p in (dri major, ox ascending) order. DO NOT REORDER
// the arithmetic — it reproduces the reference's fp tie resolution
// bit-for-bit. (Load scheduling/thread assignment changes are value-safe.)
// ---------------------------------------------------------------------------
#define CSTR2   68                    // col-slot stride (floats)
#define ROWSTR2 (38*CSTR2 + 12)       // 2596 floats; conflict-free reads
#define SV_BYTES (14*ROWSTR2*4)       // 145376 bytes dynamic smem

#define LOAD_WA(wb, ab, c4)                                                   \
    do {                                                                      \
        _Pragma("unroll")                                                     \
        for (int j = 0; j < 10; ++j)                                          \
            wb[j] = *reinterpret_cast<const float4*>(vrow + j*CSTR2 + (c4)*4);\
        _Pragma("unroll")                                                     \
        for (int ox = 0; ox < 7; ++ox)                                        \
            ab[ox] = *reinterpret_cast<const float4*>(qrow + xq[ox] + (c4)*4);\
    } while (0)

#define COMPUTE_WA(wb, ab)                                                    \
    do {                                                                      \
        _Pragma("unroll")                                                     \
        for (int d = 0; d < 4; ++d) {                                         \
            _Pragma("unroll")                                                 \
            for (int ox = 0; ox < 7; ++ox) {                                  \
                float4 b = wb[d + ox];                                        \
                p[d][ox] = fmaf(ab[ox].x, b.x, p[d][ox]);                     \
                p[d][ox] = fmaf(ab[ox].y, b.y, p[d][ox]);                     \
                p[d][ox] = fmaf(ab[ox].z, b.z, p[d][ox]);                     \
                p[d][ox] = fmaf(ab[ox].w, b.w, p[d][ox]);                     \
            }                                                                 \
        }                                                                     \
    } while (0)

__global__ void __launch_bounds__(192, 1) stage1a_kernel() {
    extern __shared__ float sv[];

    const int qj0 = blockIdx.x * 4;
    const int qi  = blockIdx.y;
    const int t   = blockIdx.z;
    const int qh  = qi * 8;
    const int qw0 = qj0 * 8;

    const int tid  = threadIdx.x;
    const int slot = tid >> 4;        // 0..11
    const int qt   = slot >> 2;       // 0..2
    const int u    = slot & 3;        // query within block
    const int sub  = tid & 15;
    const int dyi  = sub >> 1;        // 0..7
    const int quad = sub & 1;         // 0..1 -> dxi base 4*quad

    // cooperative load: candidate window (once)
    const float* v1base = g_v1t + (size_t)t*HWSZ*CC;
    for (int i = tid; i < 14*38*16; i += 192) {
        int r   = i / (38*16);
        int rem = i % (38*16);
        int s   = rem >> 4;
        int c4  = rem & 15;
        int y = refl(qh - 7 + r, HH);
        int x = refl(qw0 - 7 + s, WW);
        float4 v = reinterpret_cast<const float4*>(v1base + ((size_t)y*WW + x)*CC)[c4];
        *reinterpret_cast<float4*>(sv + r*ROWSTR2 + s*CSTR2 + c4*4) = v;
    }
    __syncthreads();

    const int q  = qt*(NHC*NWC) + qi*NWC + (qj0 + u);
    const int qw = qw0 + u*8;

    // query patch col element-offsets (uniform within slot)
    int xq[7];
    #pragma unroll
    for (int ox = 0; ox < 7; ++ox) xq[ox] = refl(qw + ox - 3, WW) * CC;
    const float* v0base = g_v0t + (size_t)qt*HWSZ*CC;

    float acc[4] = {0.f, 0.f, 0.f, 0.f};
    const float* svw = sv + (8*u + 4*quad)*CSTR2;

    for (int dri = 0; dri < 7; ++dri) {
        const int yq = refl(qh + dri - 3, HH);
        const float* qrow = v0base + (size_t)yq*WW*CC;
        const float* vrow = svw + (dyi + dri)*ROWSTR2;

        float p[4][7];
        #pragma unroll
        for (int d = 0; d < 4; ++d)
            #pragma unroll
            for (int ox = 0; ox < 7; ++ox) p[d][ox] = 0.f;

        // software pipeline: prefetch one c4-iter ahead into alternating bufs
        float4 w0[10], a0[7], w1[10], a1[7];
        LOAD_WA(w0, a0, 0);
        #pragma unroll
        for (int c4 = 0; c4 < 16; c4 += 2) {
            LOAD_WA(w1, a1, c4 + 1);     // prefetch c4+1
            COMPUTE_WA(w0, a0);          // compute c4
            if (c4 + 2 < 16)
                LOAD_WA(w0, a0, c4 + 2); // prefetch c4+2
            COMPUTE_WA(w1, a1);          // compute c4+1
        }
        #pragma unroll
        for (int d = 0; d < 4; ++d)
            #pragma unroll
            for (int ox = 0; ox < 7; ++ox) acc[d] += p[d][ox];
    }

    float4 res = make_float4(acc[0], acc[1], acc[2], acc[3]);
    *reinterpret_cast<float4*>(&g_sd[q*SS + t*64 + dyi*8 + 4*quad]) = res;
}

// ---------------------------------------------------------------------------
// Stage 1b: warp-per-query top-7 via shuffles (no block syncs).
// Stable: ties -> lowest candidate index (lax.top_k semantics).
// ---------------------------------------------------------------------------
__global__ void __launch_bounds__(256) stage1b_kernel() {
    const int lane = threadIdx.x & 31;
    const int q = blockIdx.x*8 + (threadIdx.x >> 5);
    const int rr = q % (NHC*NWC);
    const int qh = (rr / NWC) * 8;
    const int qw = (rr % NWC) * 8;

    float v[6];
    #pragma unroll
    for (int j = 0; j < 6; ++j) v[j] = g_sd[q*SS + j*32 + lane];

    #pragma unroll 1
    for (int k = 0; k < KK; ++k) {
        float bv = v[0]; int bi = lane;
        #pragma unroll
        for (int j = 1; j < 6; ++j) {
            if (v[j] > bv) { bv = v[j]; bi = j*32 + lane; }
        }
        #pragma unroll
        for (int s = 16; s > 0; s >>= 1) {
            float ov = __shfl_xor_sync(0xffffffffu, bv, s);
            int   oi = __shfl_xor_sync(0xffffffffu, bi, s);
            if (ov > bv || (ov == bv && oi < bi)) { bv = ov; bi = oi; }
        }
        if (lane == 0) {
            int base = (q*KK + k)*3;
            g_inds[base + 0] = bi >> 6;                   // ct
            g_inds[base + 1] = qh + ((bi >> 3) & 7) - 4;  // ch (raw)
            g_inds[base + 2] = qw + (bi & 7) - 4;         // cw (raw)
        }
        if ((bi & 31) == lane) {
            int jj = bi >> 5;
            #pragma unroll
            for (int j = 0; j < 6; ++j) if (j == jj) v[j] = -FLT_MAX;
        }
    }
}

// ---------------------------------------------------------------------------
// Stage 2+3 fused v5: float4 channel split (dists_f is tolerance-checked,
// so the summation order is free here — only stage1 needed bit-exactness).
// block = 224 threads (7 warps); warp k = candidate k.
// lane: par = lane>>4 (offset parity), c16 = lane&15 (channel quad).
// ---------------------------------------------------------------------------
__global__ void __launch_bounds__(224) stage3_kernel(float* __restrict__ out) {
    const int q  = blockIdx.x;
    const int ft = q / (NHF*NWF);
    const int rr = q % (NHF*NWF);
    const int fi = rr / NWF, fj = rr % NWF;
    const int fh = fi*4, fw = fj*4;

    __shared__ float sp[49*CC];
    __shared__ int   scand[KK*3];
    __shared__ int   soff[KK*49 + 7];   // padded (soff[k][49] read by par=1 tail)

    const int tid = threadIdx.x;
    // query patch, vectorized
    for (int i = tid; i < 49*16; i += 224) {
        int o = i >> 4, c4 = i & 15;
        int y = refl(fh + (o/7) - 3, HH);
        int x = refl(fw + (o%7) - 3, WW);
        reinterpret_cast<float4*>(sp)[i] =
            reinterpret_cast<const float4*>(g_v0t + ((size_t)ft*HWSZ + (size_t)y*WW + x)*CC)[c4];
    }
    if (tid < KK) {
        int it, ih, iw;
        if (tid == 0) { it = ft; ih = fh; iw = fw; }
        else {
            int ci = min(fi >> 1, NHC - 1);
            int cj = min(fj >> 1, NWC - 1);
            int qlin = ft*NHC*NWC + ci*NWC + cj;
            int b = (qlin*KK + tid)*3;
            it = g_inds[b + 0];
            ih = refl(g_inds[b + 1] + (fh - ci*8), HH);
            iw = refl(g_inds[b + 2] + (fw - cj*8), WW);
        }
        scand[tid*3 + 0] = it;
        scand[tid*3 + 1] = ih;
        scand[tid*3 + 2] = iw;
        soff[KK*49 + tid] = 0;   // safe pad
        // inds_f (as float), laid out after dists_f
        size_t ob = (size_t)QF*KK + ((size_t)q*KK + tid)*3;
        out[ob + 0] = (float)it;
        out[ob + 1] = (float)ih;
        out[ob + 2] = (float)iw;
    }
    __syncthreads();

    // cooperative offset table: soff[k*49+o] = (y1*W + x1)*CC (element offset)
    for (int i = tid; i < KK*49; i += 224) {
        int k = i / 49, o = i % 49;
        int y1 = refl(scand[k*3 + 1] + o/7 - 3, HH);
        int x1 = refl(scand[k*3 + 2] + o%7 - 3, WW);
        soff[i] = (y1*WW + x1)*CC;
    }
    __syncthreads();

    const int warp = tid >> 5;
    const int lane = tid & 31;
    const int par  = lane >> 4;       // offset parity
    const int c16  = lane & 15;       // channel quad
    const int it = scand[warp*3 + 0];
    const float* v1b = g_v1t + (size_t)it*HWSZ*CC + 4*c16;
    const int* mysoff = soff + warp*49 + par;
    const float* spl = sp + 4*c16;

    float4 acc = make_float4(0.f, 0.f, 0.f, 0.f);
    #pragma unroll 5
    for (int i = 0; i < 25; ++i) {
        int o = 2*i + par;            // par=1,i=24 -> o=49 reads pad; masked below
        float4 wv = *reinterpret_cast<const float4*>(v1b + mysoff[2*i]);
        float4 pv = *reinterpret_cast<const float4*>(spl + o*CC);
        float m = (o < 49) ? 1.f : 0.f;
        acc.x = fmaf(pv.x*m, wv.x, acc.x);
        acc.y = fmaf(pv.y*m, wv.y, acc.y);
        acc.z = fmaf(pv.z*m, wv.z, acc.z);
        acc.w = fmaf(pv.w*m, wv.w, acc.w);
    }
    float v = (acc.x + acc.y) + (acc.z + acc.w);
    #pragma unroll
    for (int s = 16; s > 0; s >>= 1)
        v += __shfl_down_sync(0xffffffffu, v, s);
    if (lane == 0)
        out[(size_t)q*KK + warp] = v;
}

// ---------------------------------------------------------------------------
extern "C" void kernel_launch(void* const* d_in, const int* in_sizes, int n_in,
                              void* d_out, int out_size) {
    const float* vid0 = (const float*)d_in[0];
    const float* vid1 = (const float*)d_in[1];
    // d_in[2] = flows, unused by the reference

    cudaFuncSetAttribute(stage1a_kernel,
                         cudaFuncAttributeMaxDynamicSharedMemorySize, SV_BYTES);

    // two dummies keep the ncu fixed capture slot on stage1a
    dummy_kernel<<<1, 32>>>();
    dummy_kernel<<<1, 32>>>();

    dim3 tgrid(HWSZ/32, TT, 2);
    transpose_kernel<<<tgrid, 256>>>(vid0, vid1);
    stage1a_kernel<<<dim3(NWC/4, NHC, TT), 192, SV_BYTES>>>();
    stage1b_kernel<<<Q1/8, 256>>>();
    stage3_kernel<<<QF, 224>>>((float*)d_out);
}

// round 12
// speedup vs baseline: 2.5120x; 1.0262x over previous
#include <cuda_runtime.h>
#include <float.h>

#define TT   3
#define HH   192
#define WW   192
#define CC   64
#define HWSZ (HH*WW)
#define NHC  24
#define NWC  24
#define Q1   (TT*NHC*NWC)   // 1728
#define NHF  48
#define NWF  48
#define QF   (TT*NHF*NWF)   // 6912
#define KK   7
#define SS   192            // candidates per query

// scratch (static __device__ arrays — allowed; no runtime allocation)
__device__ float g_v0t[TT*HWSZ*CC];
__device__ float g_v1t[TT*HWSZ*CC];
__device__ float g_sd[Q1*SS];
__device__ int   g_inds[Q1*KK*3];

__device__ __forceinline__ int refl(int i, int L) {
    i = i < 0 ? -i : i;
    return (i >= L) ? (2*(L-1) - i) : i;
}

// rotate the ncu fixed capture slot onto stage1a (diagnostic)
__global__ void dummy_kernel() {}

// ---------------------------------------------------------------------------
// Transpose (T,C,H,W) -> (T,H,W,C), channels-last, for both videos.
// ---------------------------------------------------------------------------
__global__ void __launch_bounds__(256) transpose_kernel(const float* __restrict__ v0,
                                                        const float* __restrict__ v1) {
    const float* src = (blockIdx.z == 0) ? v0 : v1;
    float* dst       = (blockIdx.z == 0) ? g_v0t : g_v1t;
    const int t    = blockIdx.y;
    const int pix0 = blockIdx.x * 32;

    __shared__ float tile[CC][33];
    const int tx  = threadIdx.x & 31;
    const int grp = threadIdx.x >> 5;   // 0..7

    #pragma unroll
    for (int cc = 0; cc < CC; cc += 8) {
        int c = cc + grp;
        tile[c][tx] = src[((size_t)(t*CC + c))*HWSZ + pix0 + tx];
    }
    __syncthreads();
    #pragma unroll
    for (int i = 0; i < 8; ++i) {
        int idx = i*256 + threadIdx.x;        // 0..2047
        int pix = idx >> 6;                   // 0..31
        int ch  = idx & 63;
        dst[((size_t)t*HWSZ + pix0 + pix)*CC + ch] = tile[ch][pix];
    }
}

// ---------------------------------------------------------------------------
// Stage 1a v9: 6-query blocks for balanced SMSPs + fewer waves.
// grid (4, 24, 3): block = (6 adjacent queries, row qi, t). 288 thr = 9 warps.
// query-slot = tid>>4 (0..17): u = slot%6, qt = slot/6.
// within slot: sub = tid&15; dyi = sub>>1, quad = sub&1; thread owns
// candidates dxi = 4*quad .. 4*quad+3 (quad packing, 28 FMA4 per 17 loads).
// Candidate window 14 rows x 54 col-slots x 64ch in smem (206 KB), loaded
// once; query-patch via slot-uniform LDG.128.
// Per candidate, per offset (dri,ox): p = sequential fma chain over c=0..63,
// then acc += p in (dri major, ox ascending) order. DO NOT REORDER the
// arithmetic — it reproduces the reference's fp tie resolution bit-for-bit.
// ---------------------------------------------------------------------------
#define NQB     6                     // queries per block
#define WCOLS   (8*NQB + 6)           // 54 col slots
#define CSTR2   68                    // col-slot stride (floats)
#define ROWSTR2 (WCOLS*CSTR2 + 12)    // 3684 floats; mod 32 == 4 (conflict-free)
#define SV_BYTES (14*ROWSTR2*4)       // 206304 bytes dynamic smem

#define LOAD_WA(wb, ab, c4)                                                   \
    do {                                                                      \
        _Pragma("unroll")                                                     \
        for (int j = 0; j < 10; ++j)                                          \
            wb[j] = *reinterpret_cast<const float4*>(vrow + j*CSTR2 + (c4)*4);\
        _Pragma("unroll")                                                     \
        for (int ox = 0; ox < 7; ++ox)                                        \
            ab[ox] = *reinterpret_cast<const float4*>(qrow + xq[ox] + (c4)*4);\
    } while (0)

#define COMPUTE_WA(wb, ab)                                                    \
    do {                                                                      \
        _Pragma("unroll")                                                     \
        for (int d = 0; d < 4; ++d) {                                         \
            _Pragma("unroll")                                                 \
            for (int ox = 0; ox < 7; ++ox) {                                  \
                float4 b = wb[d + ox];                                        \
                p[d][ox] = fmaf(ab[ox].x, b.x, p[d][ox]);                     \
                p[d][ox] = fmaf(ab[ox].y, b.y, p[d][ox]);                     \
                p[d][ox] = fmaf(ab[ox].z, b.z, p[d][ox]);                     \
                p[d][ox] = fmaf(ab[ox].w, b.w, p[d][ox]);                     \
            }                                                                 \
        }                                                                     \
    } while (0)

__global__ void __launch_bounds__(288, 1) stage1a_kernel() {
    extern __shared__ float sv[];

    const int qj0 = blockIdx.x * NQB;
    const int qi  = blockIdx.y;
    const int t   = blockIdx.z;
    const int qh  = qi * 8;
    const int qw0 = qj0 * 8;

    const int tid  = threadIdx.x;
    const int slot = tid >> 4;        // 0..17
    const int u    = slot % NQB;      // query within block
    const int qt   = slot / NQB;      // 0..2
    const int sub  = tid & 15;
    const int dyi  = sub >> 1;        // 0..7
    const int quad = sub & 1;         // 0..1 -> dxi base 4*quad

    // cooperative load: candidate window (once)
    const float* v1base = g_v1t + (size_t)t*HWSZ*CC;
    for (int i = tid; i < 14*WCOLS*16; i += 288) {
        int r   = i / (WCOLS*16);
        int rem = i % (WCOLS*16);
        int s   = rem >> 4;
        int c4  = rem & 15;
        int y = refl(qh - 7 + r, HH);
        int x = refl(qw0 - 7 + s, WW);
        float4 v = reinterpret_cast<const float4*>(v1base + ((size_t)y*WW + x)*CC)[c4];
        *reinterpret_cast<float4*>(sv + r*ROWSTR2 + s*CSTR2 + c4*4) = v;
    }
    __syncthreads();

    const int q  = qt*(NHC*NWC) + qi*NWC + (qj0 + u);
    const int qw = qw0 + u*8;

    // query patch col element-offsets (uniform within slot)
    int xq[7];
    #pragma unroll
    for (int ox = 0; ox < 7; ++ox) xq[ox] = refl(qw + ox - 3, WW) * CC;
    const float* v0base = g_v0t + (size_t)qt*HWSZ*CC;

    float acc[4] = {0.f, 0.f, 0.f, 0.f};
    const float* svw = sv + (8*u + 4*quad)*CSTR2;

    for (int dri = 0; dri < 7; ++dri) {
        const int yq = refl(qh + dri - 3, HH);
        const float* qrow = v0base + (size_t)yq*WW*CC;
        const float* vrow = svw + (dyi + dri)*ROWSTR2;

        float p[4][7];
        #pragma unroll
        for (int d = 0; d < 4; ++d)
            #pragma unroll
            for (int ox = 0; ox < 7; ++ox) p[d][ox] = 0.f;

        // software pipeline: prefetch one c4-iter ahead into alternating bufs
        float4 w0[10], a0[7], w1[10], a1[7];
        LOAD_WA(w0, a0, 0);
        #pragma unroll
        for (int c4 = 0; c4 < 16; c4 += 2) {
            LOAD_WA(w1, a1, c4 + 1);     // prefetch c4+1
            COMPUTE_WA(w0, a0);          // compute c4
            if (c4 + 2 < 16)
                LOAD_WA(w0, a0, c4 + 2); // prefetch c4+2
            COMPUTE_WA(w1, a1);          // compute c4+1
        }
        #pragma unroll
        for (int d = 0; d < 4; ++d)
            #pragma unroll
            for (int ox = 0; ox < 7; ++ox) acc[d] += p[d][ox];
    }

    float4 res = make_float4(acc[0], acc[1], acc[2], acc[3]);
    *reinterpret_cast<float4*>(&g_sd[q*SS + t*64 + dyi*8 + 4*quad]) = res;
}

// ---------------------------------------------------------------------------
// Stage 1b: warp-per-query top-7 via shuffles (no block syncs).
// Stable: ties -> lowest candidate index (lax.top_k semantics).
// ---------------------------------------------------------------------------
__global__ void __launch_bounds__(256) stage1b_kernel() {
    const int lane = threadIdx.x & 31;
    const int q = blockIdx.x*8 + (threadIdx.x >> 5);
    const int rr = q % (NHC*NWC);
    const int qh = (rr / NWC) * 8;
    const int qw = (rr % NWC) * 8;

    float v[6];
    #pragma unroll
    for (int j = 0; j < 6; ++j) v[j] = g_sd[q*SS + j*32 + lane];

    #pragma unroll 1
    for (int k = 0; k < KK; ++k) {
        float bv = v[0]; int bi = lane;
        #pragma unroll
        for (int j = 1; j < 6; ++j) {
            if (v[j] > bv) { bv = v[j]; bi = j*32 + lane; }
        }
        #pragma unroll
        for (int s = 16; s > 0; s >>= 1) {
            float ov = __shfl_xor_sync(0xffffffffu, bv, s);
            int   oi = __shfl_xor_sync(0xffffffffu, bi, s);
            if (ov > bv || (ov == bv && oi < bi)) { bv = ov; bi = oi; }
        }
        if (lane == 0) {
            int base = (q*KK + k)*3;
            g_inds[base + 0] = bi >> 6;                   // ct
            g_inds[base + 1] = qh + ((bi >> 3) & 7) - 4;  // ch (raw)
            g_inds[base + 2] = qw + (bi & 7) - 4;         // cw (raw)
        }
        if ((bi & 31) == lane) {
            int jj = bi >> 5;
            #pragma unroll
            for (int j = 0; j < 6; ++j) if (j == jj) v[j] = -FLT_MAX;
        }
    }
}

// ---------------------------------------------------------------------------
// Stage 2+3 fused v5: float4 channel split (dists_f is tolerance-checked,
// so the summation order is free here — only stage1 needed bit-exactness).
// block = 224 threads (7 warps); warp k = candidate k.
// lane: par = lane>>4 (offset parity), c16 = lane&15 (channel quad).
// ---------------------------------------------------------------------------
__global__ void __launch_bounds__(224) stage3_kernel(float* __restrict__ out) {
    const int q  = blockIdx.x;
    const int ft = q / (NHF*NWF);
    const int rr = q % (NHF*NWF);
    const int fi = rr / NWF, fj = rr % NWF;
    const int fh = fi*4, fw = fj*4;

    __shared__ float sp[49*CC];
    __shared__ int   scand[KK*3];
    __shared__ int   soff[KK*49 + 7];   // padded (soff[k][49] read by par=1 tail)

    const int tid = threadIdx.x;
    // query patch, vectorized
    for (int i = tid; i < 49*16; i += 224) {
        int o = i >> 4, c4 = i & 15;
        int y = refl(fh + (o/7) - 3, HH);
        int x = refl(fw + (o%7) - 3, WW);
        reinterpret_cast<float4*>(sp)[i] =
            reinterpret_cast<const float4*>(g_v0t + ((size_t)ft*HWSZ + (size_t)y*WW + x)*CC)[c4];
    }
    if (tid < KK) {
        int it, ih, iw;
        if (tid == 0) { it = ft; ih = fh; iw = fw; }
        else {
            int ci = min(fi >> 1, NHC - 1);
            int cj = min(fj >> 1, NWC - 1);
            int qlin = ft*NHC*NWC + ci*NWC + cj;
            int b = (qlin*KK + tid)*3;
            it = g_inds[b + 0];
            ih = refl(g_inds[b + 1] + (fh - ci*8), HH);
            iw = refl(g_inds[b + 2] + (fw - cj*8), WW);
        }
        scand[tid*3 + 0] = it;
        scand[tid*3 + 1] = ih;
        scand[tid*3 + 2] = iw;
        soff[KK*49 + tid] = 0;   // safe pad
        // inds_f (as float), laid out after dists_f
        size_t ob = (size_t)QF*KK + ((size_t)q*KK + tid)*3;
        out[ob + 0] = (float)it;
        out[ob + 1] = (float)ih;
        out[ob + 2] = (float)iw;
    }
    __syncthreads();

    // cooperative offset table: soff[k*49+o] = (y1*W + x1)*CC (element offset)
    for (int i = tid; i < KK*49; i += 224) {
        int k = i / 49, o = i % 49;
        int y1 = refl(scand[k*3 + 1] + o/7 - 3, HH);
        int x1 = refl(scand[k*3 + 2] + o%7 - 3, WW);
        soff[i] = (y1*WW + x1)*CC;
    }
    __syncthreads();

    const int warp = tid >> 5;
    const int lane = tid & 31;
    const int par  = lane >> 4;       // offset parity
    const int c16  = lane & 15;       // channel quad
    const int it = scand[warp*3 + 0];
    const float* v1b = g_v1t + (size_t)it*HWSZ*CC + 4*c16;
    const int* mysoff = soff + warp*49 + par;
    const float* spl = sp + 4*c16;

    float4 acc = make_float4(0.f, 0.f, 0.f, 0.f);
    #pragma unroll 5
    for (int i = 0; i < 25; ++i) {
        int o = 2*i + par;            // par=1,i=24 -> o=49 reads pad; masked below
        float4 wv = *reinterpret_cast<const float4*>(v1b + mysoff[2*i]);
        float4 pv = *reinterpret_cast<const float4*>(spl + o*CC);
        float m = (o < 49) ? 1.f : 0.f;
        acc.x = fmaf(pv.x*m, wv.x, acc.x);
        acc.y = fmaf(pv.y*m, wv.y, acc.y);
        acc.z = fmaf(pv.z*m, wv.z, acc.z);
        acc.w = fmaf(pv.w*m, wv.w, acc.w);
    }
    float v = (acc.x + acc.y) + (acc.z + acc.w);
    #pragma unroll
    for (int s = 16; s > 0; s >>= 1)
        v += __shfl_down_sync(0xffffffffu, v, s);
    if (lane == 0)
        out[(size_t)q*KK + warp] = v;
}

// ---------------------------------------------------------------------------
extern "C" void kernel_launch(void* const* d_in, const int* in_sizes, int n_in,
                              void* d_out, int out_size) {
    const float* vid0 = (const float*)d_in[0];
    const float* vid1 = (const float*)d_in[1];
    // d_in[2] = flows, unused by the reference

    cudaFuncSetAttribute(stage1a_kernel,
                         cudaFuncAttributeMaxDynamicSharedMemorySize, SV_BYTES);

    // two dummies keep the ncu fixed capture slot on stage1a
    dummy_kernel<<<1, 32>>>();
    dummy_kernel<<<1, 32>>>();

    dim3 tgrid(HWSZ/32, TT, 2);
    transpose_kernel<<<tgrid, 256>>>(vid0, vid1);
    stage1a_kernel<<<dim3(NWC/NQB, NHC, TT), 288, SV_BYTES>>>();
    stage1b_kernel<<<Q1/8, 256>>>();
    stage3_kernel<<<QF, 224>>>((float*)d_out);
}